// round 1
// baseline (speedup 1.0000x reference)
#include <cuda_runtime.h>
#include <math.h>

#define BATCH 4
#define CC    256
#define CQ    32
#define NTOK  4096

// scratch (allocation-free rule: __device__ globals)
__device__ float g_q[BATCH * CQ * NTOK];
__device__ float g_k[BATCH * CQ * NTOK];
__device__ float g_v[BATCH * CC * NTOK];

// ---------- packed f32x2 helpers ----------
__device__ __forceinline__ unsigned long long pack2(float lo, float hi) {
    unsigned long long r;
    asm("mov.b64 %0, {%1,%2};" : "=l"(r) : "f"(lo), "f"(hi));
    return r;
}
__device__ __forceinline__ void unpack2(unsigned long long v, float& lo, float& hi) {
    asm("mov.b64 {%0,%1}, %2;" : "=f"(lo), "=f"(hi) : "l"(v));
}
__device__ __forceinline__ unsigned long long fma2(unsigned long long a,
                                                   unsigned long long b,
                                                   unsigned long long c) {
    unsigned long long d;
    asm("fma.rn.f32x2 %0, %1, %2, %3;" : "=l"(d) : "l"(a), "l"(b), "l"(c));
    return d;
}
__device__ __forceinline__ unsigned long long mul2(unsigned long long a,
                                                   unsigned long long b) {
    unsigned long long d;
    asm("mul.rn.f32x2 %0, %1, %2;" : "=l"(d) : "l"(a), "l"(b));
    return d;
}

// =====================================================================
// Kernel 1: 1x1-conv projections. out rows: [0,32)=q, [32,64)=k, [64,320)=v
// grid: (32 n-tiles of 128, 5 row-tiles of 64, 4 batches), 256 threads
// =====================================================================
__global__ __launch_bounds__(256) void proj_kernel(
    const float* __restrict__ x,
    const float* __restrict__ wq, const float* __restrict__ bq,
    const float* __restrict__ wk, const float* __restrict__ bk,
    const float* __restrict__ wv, const float* __restrict__ bv)
{
    __shared__ float sX[32 * 128];   // [c_local][n_local]
    __shared__ float sW[32 * 68];    // [c_local][r_local] padded

    const int n0 = blockIdx.x * 128;
    const int r0 = blockIdx.y * 64;
    const int b  = blockIdx.z;
    const int t  = threadIdx.x;
    const int rg = t >> 4;           // 0..15 -> rows 4*rg..4*rg+3
    const int ng = t & 15;           // 0..15 -> cols 4*ng.. and 64+4*ng..

    float acc[4][8];
#pragma unroll
    for (int j = 0; j < 4; j++)
#pragma unroll
        for (int i = 0; i < 8; i++) acc[j][i] = 0.0f;

    for (int cc = 0; cc < CC; cc += 32) {
        // load X tile [32][128]
#pragma unroll
        for (int p = 0; p < 4; p++) {
            int idx = p * 256 + t;               // 0..1023 float4s
            int cr = idx >> 5, l = idx & 31;
            float4 v = *(const float4*)(x + ((size_t)b * CC + cc + cr) * NTOK + n0 + 4 * l);
            *(float4*)(sX + cr * 128 + 4 * l) = v;
        }
        // load W tile transposed sW[c][r]
#pragma unroll
        for (int p = 0; p < 2; p++) {
            int idx = p * 256 + t;               // 0..511
            int rl = idx >> 3, cf = idx & 7;     // rl 0..63, cf 0..7
            int rglob = r0 + rl;
            const float* wrow;
            if (rglob < CQ)          wrow = wq + (size_t)rglob * CC;
            else if (rglob < 2 * CQ) wrow = wk + (size_t)(rglob - CQ) * CC;
            else                     wrow = wv + (size_t)(rglob - 2 * CQ) * CC;
            float4 v = *(const float4*)(wrow + cc + 4 * cf);
            sW[(4 * cf + 0) * 68 + rl] = v.x;
            sW[(4 * cf + 1) * 68 + rl] = v.y;
            sW[(4 * cf + 2) * 68 + rl] = v.z;
            sW[(4 * cf + 3) * 68 + rl] = v.w;
        }
        __syncthreads();

#pragma unroll
        for (int c = 0; c < 32; c++) {
            float4 w  = *(float4*)(sW + c * 68 + 4 * rg);
            float4 x1 = *(float4*)(sX + c * 128 + 4 * ng);
            float4 x2 = *(float4*)(sX + c * 128 + 64 + 4 * ng);
            float wj[4] = {w.x, w.y, w.z, w.w};
            float xs[8] = {x1.x, x1.y, x1.z, x1.w, x2.x, x2.y, x2.z, x2.w};
#pragma unroll
            for (int j = 0; j < 4; j++)
#pragma unroll
                for (int i = 0; i < 8; i++) acc[j][i] = fmaf(wj[j], xs[i], acc[j][i]);
        }
        __syncthreads();
    }

#pragma unroll
    for (int j = 0; j < 4; j++) {
        int rglob = r0 + 4 * rg + j;
        float bias;
        float* dst;
        if (rglob < CQ)          { bias = bq[rglob];          dst = g_q + ((size_t)b * CQ + rglob) * NTOK; }
        else if (rglob < 2 * CQ) { bias = bk[rglob - CQ];     dst = g_k + ((size_t)b * CQ + rglob - CQ) * NTOK; }
        else                     { bias = bv[rglob - 2 * CQ]; dst = g_v + ((size_t)b * CC + rglob - 2 * CQ) * NTOK; }
        float4 o1 = {acc[j][0] + bias, acc[j][1] + bias, acc[j][2] + bias, acc[j][3] + bias};
        float4 o2 = {acc[j][4] + bias, acc[j][5] + bias, acc[j][6] + bias, acc[j][7] + bias};
        *(float4*)(dst + n0 + 4 * ng)      = o1;
        *(float4*)(dst + n0 + 64 + 4 * ng) = o2;
    }
}

// =====================================================================
// Kernel 2: flash attention (fp32, packed f32x2 PV) + residual epilogue
// grid: 256 CTAs = 4 batches x 64 query-tiles(64), 256 threads
// thread (mg = t/16, ng = t%16): queries m = 4*mg+j, channels o = ng+16*i
// =====================================================================
#define SMEM_FLOATS (256 * 65 + 32 * 64 + 32 * 64 + 64 * 68)

__global__ __launch_bounds__(256, 2) void attn_kernel(
    const float* __restrict__ x,
    const float* __restrict__ gamma,
    float* __restrict__ out)
{
    extern __shared__ float sm[];
    float* sV  = sm;                       // [256][65]  padded V tile (o-major)
    float* sQ  = sm + 256 * 65;            // [32][64]   Q tile (c-major)
    float* sK  = sQ + 32 * 64;             // [32][64]   K tile (c-major)
    float* sPt = sK + 32 * 64;             // [64][68]   P transposed [n'][m]

    const int t  = threadIdx.x;
    const int mg = t >> 4;                 // 0..15
    const int ng = t & 15;                 // 0..15
    const int b  = blockIdx.x >> 6;
    const int q0 = (blockIdx.x & 63) * 64;

    const float* qb = g_q + (size_t)b * CQ * NTOK;
    const float* kb = g_k + (size_t)b * CQ * NTOK;
    const float* vb = g_v + (size_t)b * CC * NTOK;

    // load Q tile once: sQ[c][m]
#pragma unroll
    for (int p = 0; p < 2; p++) {
        int idx = p * 256 + t;             // 0..511 float4s
        int c = idx >> 4, l = idx & 15;
        float4 v = *(const float4*)(qb + (size_t)c * NTOK + q0 + 4 * l);
        *(float4*)(sQ + c * 64 + 4 * l) = v;
    }

    unsigned long long acc[2][16];         // [query-pair][channel], f32x2 packed
#pragma unroll
    for (int jp = 0; jp < 2; jp++)
#pragma unroll
        for (int i = 0; i < 16; i++) acc[jp][i] = 0ull;

    float run_m[4] = {-INFINITY, -INFINITY, -INFINITY, -INFINITY};
    float run_l[4] = {0.f, 0.f, 0.f, 0.f};

    for (int j0 = 0; j0 < NTOK; j0 += 64) {
        __syncthreads();   // previous PV finished reading sV/sPt
        // load K tile
#pragma unroll
        for (int p = 0; p < 2; p++) {
            int idx = p * 256 + t;
            int c = idx >> 4, l = idx & 15;
            float4 v = *(const float4*)(kb + (size_t)c * NTOK + j0 + 4 * l);
            *(float4*)(sK + c * 64 + 4 * l) = v;
        }
        // load V tile: sV[o][n'] stride 65 (conflict-free reads with o=ng+16i)
#pragma unroll
        for (int p = 0; p < 16; p++) {
            int idx = p * 256 + t;         // 0..4095 float4s
            int o = idx >> 4, l = idx & 15;
            float4 v = *(const float4*)(vb + (size_t)o * NTOK + j0 + 4 * l);
            float* d = sV + o * 65 + 4 * l;
            d[0] = v.x; d[1] = v.y; d[2] = v.z; d[3] = v.w;
        }
        __syncthreads();

        // ---- S = Q Kᵀ (fp32, exact scores) ----
        float s[4][4];
#pragma unroll
        for (int j = 0; j < 4; j++)
#pragma unroll
            for (int i = 0; i < 4; i++) s[j][i] = 0.0f;
#pragma unroll
        for (int c = 0; c < 32; c++) {
            float4 q = *(float4*)(sQ + c * 64 + 4 * mg);
            float4 k = *(float4*)(sK + c * 64 + 4 * ng);
            float qj[4] = {q.x, q.y, q.z, q.w};
            float ki[4] = {k.x, k.y, k.z, k.w};
#pragma unroll
            for (int j = 0; j < 4; j++)
#pragma unroll
                for (int i = 0; i < 4; i++) s[j][i] = fmaf(qj[j], ki[i], s[j][i]);
        }

        // ---- online softmax (shfl over the 16 ng lanes) ----
        float p[4][4], alpha[4];
#pragma unroll
        for (int j = 0; j < 4; j++) {
            float rm = fmaxf(fmaxf(s[j][0], s[j][1]), fmaxf(s[j][2], s[j][3]));
#pragma unroll
            for (int d = 1; d < 16; d <<= 1)
                rm = fmaxf(rm, __shfl_xor_sync(0xffffffffu, rm, d));
            float mnew = fmaxf(run_m[j], rm);
            alpha[j] = __expf(run_m[j] - mnew);
            float rs = 0.0f;
#pragma unroll
            for (int i = 0; i < 4; i++) {
                p[j][i] = __expf(s[j][i] - mnew);
                rs += p[j][i];
            }
#pragma unroll
            for (int d = 1; d < 16; d <<= 1)
                rs += __shfl_xor_sync(0xffffffffu, rs, d);
            run_l[j] = run_l[j] * alpha[j] + rs;
            run_m[j] = mnew;
        }

        // write P transposed: sPt[n'][m]
#pragma unroll
        for (int i = 0; i < 4; i++) {
            float4 v = {p[0][i], p[1][i], p[2][i], p[3][i]};
            *(float4*)(sPt + (4 * ng + i) * 68 + 4 * mg) = v;
        }

        // rescale accumulators by alpha (packed)
        unsigned long long a01 = pack2(alpha[0], alpha[1]);
        unsigned long long a23 = pack2(alpha[2], alpha[3]);
#pragma unroll
        for (int i = 0; i < 16; i++) {
            acc[0][i] = mul2(acc[0][i], a01);
            acc[1][i] = mul2(acc[1][i], a23);
        }
        __syncthreads();

        // ---- PV: acc[m][o] += sum_n' P[m][n'] * V[o][n'] (f32x2) ----
#pragma unroll 2
        for (int n = 0; n < 64; n++) {
            float4 pv = *(float4*)(sPt + n * 68 + 4 * mg);
            unsigned long long p01 = pack2(pv.x, pv.y);
            unsigned long long p23 = pack2(pv.z, pv.w);
#pragma unroll
            for (int i = 0; i < 16; i++) {
                float v = sV[(ng + 16 * i) * 65 + n];
                unsigned long long vv = pack2(v, v);
                acc[0][i] = fma2(p01, vv, acc[0][i]);
                acc[1][i] = fma2(p23, vv, acc[1][i]);
            }
        }
    }

    // ---- epilogue: out = gamma*acc/l + x ----
    float gm = gamma[0];
    float sc[4];
#pragma unroll
    for (int j = 0; j < 4; j++) sc[j] = gm / run_l[j];

    const float* xb = x   + (size_t)b * CC * NTOK;
    float*       ob = out + (size_t)b * CC * NTOK;
#pragma unroll
    for (int i = 0; i < 16; i++) {
        int o = ng + 16 * i;
        float a0, a1, a2, a3;
        unpack2(acc[0][i], a0, a1);
        unpack2(acc[1][i], a2, a3);
        size_t base = (size_t)o * NTOK + q0 + 4 * mg;
        float4 xv = *(const float4*)(xb + base);
        float4 r = {fmaf(sc[0], a0, xv.x), fmaf(sc[1], a1, xv.y),
                    fmaf(sc[2], a2, xv.z), fmaf(sc[3], a3, xv.w)};
        *(float4*)(ob + base) = r;
    }
}

// =====================================================================
extern "C" void kernel_launch(void* const* d_in, const int* in_sizes, int n_in,
                              void* d_out, int out_size)
{
    const float* x     = (const float*)d_in[0];
    const float* wq    = (const float*)d_in[1];
    const float* bq    = (const float*)d_in[2];
    const float* wk    = (const float*)d_in[3];
    const float* bk    = (const float*)d_in[4];
    const float* wv    = (const float*)d_in[5];
    const float* bv    = (const float*)d_in[6];
    const float* gamma = (const float*)d_in[7];
    float* out = (float*)d_out;

    dim3 pgrid(NTOK / 128, 5, BATCH);
    proj_kernel<<<pgrid, 256>>>(x, wq, bq, wk, bk, wv, bv);

    const int smem_bytes = SMEM_FLOATS * (int)sizeof(float);   // 100352
    cudaFuncSetAttribute(attn_kernel, cudaFuncAttributeMaxDynamicSharedMemorySize, smem_bytes);
    attn_kernel<<<BATCH * (NTOK / 64), 256, smem_bytes>>>(x, gamma, out);
}